// round 1
// baseline (speedup 1.0000x reference)
#include <cuda_runtime.h>
#include <math.h>

// Problem constants
#define B_   4
#define S_   2048
#define D_   1024
#define H_   16
#define DK_  64
#define BSZ  (B_*S_)          // 8192 rows

// ---------------- scratch (no allocations allowed) ----------------
__device__ float g_Wqp[D_*D_];       // packed [D, H*64]
__device__ float g_Wkp[D_*D_];
__device__ float g_Wvp[D_*D_];
__device__ float g_Q[(size_t)BSZ*D_];
__device__ float g_K[(size_t)BSZ*D_];
__device__ float g_V[(size_t)BSZ*D_];
__device__ float g_heads[(size_t)BSZ*D_];

// ---------------- weight pack: [H, D, 64] -> [D, H*64] ----------------
__global__ void pack_weights(const float* __restrict__ Wq,
                             const float* __restrict__ Wk,
                             const float* __restrict__ Wv) {
    int idx = blockIdx.x * blockDim.x + threadIdx.x;
    if (idx >= D_ * D_) return;
    int k = idx & 63;
    int d = (idx >> 6) & (D_ - 1);
    int h = idx >> 16;                      // idx / (D_*64)
    int o = d * D_ + h * DK_ + k;
    g_Wqp[o] = Wq[idx];
    g_Wkp[o] = Wk[idx];
    g_Wvp[o] = Wv[idx];
}

// ---------------- fp32 SGEMM: C[M,N] = A[M,K] * B[K,N], all row-major ----------------
// 128x128 block tile, BK=16, 8x8 per-thread microtile, 256 threads.
// All dims here are multiples of tile sizes (8192/1024/1024) -> no bounds checks.
#define BM 128
#define BN 128
#define BKK 16
#define TM 8
#define TN 8

__global__ __launch_bounds__(256)
void sgemm128(const float* __restrict__ A, const float* __restrict__ Bm,
              float* __restrict__ C, int M, int N, int K) {
    __shared__ float As[BKK][BM];   // stored transposed
    __shared__ float Bs[BKK][BN];

    const int tid = threadIdx.x;
    const int tx = tid & 15;
    const int ty = tid >> 4;
    const int row0 = blockIdx.y * BM;
    const int col0 = blockIdx.x * BN;

    float acc[TM][TN];
#pragma unroll
    for (int i = 0; i < TM; i++)
#pragma unroll
        for (int j = 0; j < TN; j++) acc[i][j] = 0.f;

    for (int k0 = 0; k0 < K; k0 += BKK) {
        // A tile 128x16 = 512 float4 ; B tile 16x128 = 512 float4
#pragma unroll
        for (int t = 0; t < 2; t++) {
            int idx = tid + t * 256;
            int ar  = idx >> 2;     // 0..127
            int ac4 = idx & 3;      // 0..3
            float4 v = *(const float4*)(A + (size_t)(row0 + ar) * K + k0 + ac4 * 4);
            As[ac4 * 4 + 0][ar] = v.x;
            As[ac4 * 4 + 1][ar] = v.y;
            As[ac4 * 4 + 2][ar] = v.z;
            As[ac4 * 4 + 3][ar] = v.w;
            int br  = idx >> 5;     // 0..15
            int bc4 = idx & 31;     // 0..31
            float4 w = *(const float4*)(Bm + (size_t)(k0 + br) * N + col0 + bc4 * 4);
            *(float4*)&Bs[br][bc4 * 4] = w;
        }
        __syncthreads();

#pragma unroll
        for (int kk = 0; kk < BKK; kk++) {
            float ra[TM], rb[TN];
            *(float4*)&ra[0] = *(const float4*)&As[kk][ty * TM];
            *(float4*)&ra[4] = *(const float4*)&As[kk][ty * TM + 4];
            *(float4*)&rb[0] = *(const float4*)&Bs[kk][tx * TN];
            *(float4*)&rb[4] = *(const float4*)&Bs[kk][tx * TN + 4];
#pragma unroll
            for (int i = 0; i < TM; i++)
#pragma unroll
                for (int j = 0; j < TN; j++)
                    acc[i][j] = fmaf(ra[i], rb[j], acc[i][j]);
        }
        __syncthreads();
    }

#pragma unroll
    for (int i = 0; i < TM; i++) {
        float* cp = C + (size_t)(row0 + ty * TM + i) * N + col0 + tx * TN;
        *(float4*)(cp)     = make_float4(acc[i][0], acc[i][1], acc[i][2], acc[i][3]);
        *(float4*)(cp + 4) = make_float4(acc[i][4], acc[i][5], acc[i][6], acc[i][7]);
    }
}

// ---------------- flash attention ----------------
// One CTA per (b, h, 128-query tile). 256 threads (16x16).
// Smem: Qs[64][128] (Q^T, pre-scaled), Ks[64][128] (K^T), Vs[128][64], Ps[128][128].
// Per-thread: S microtile 8x8 (rows ty*8.., cols tx*8..), O microtile 8x4 (cols tx*4..).
#define BQ 128
#define BKV 128
#define ATT_SMEM ((64*128 + 64*128 + 128*64 + 128*128) * (int)sizeof(float))  // 163840 B

__global__ __launch_bounds__(256)
void attention_kernel() {
    extern __shared__ float smem[];
    float* Qs = smem;                  // [64][128]
    float* Ks = Qs + 64 * 128;         // [64][128]
    float* Vs = Ks + 64 * 128;         // [128][64]
    float* Ps = Vs + 128 * 64;         // [128][128]

    const int tid = threadIdx.x;
    const int tx = tid & 15;
    const int ty = tid >> 4;
    const int qt = blockIdx.x;
    const int h  = blockIdx.y;
    const int b  = blockIdx.z;

    const float* Qg = g_Q + ((size_t)b * S_ + qt * BQ) * D_ + h * DK_;
    const float* Kg = g_K + ((size_t)b * S_) * D_ + h * DK_;
    const float* Vg = g_V + ((size_t)b * S_) * D_ + h * DK_;

    // Load Q tile (128 x 64), transposed into Qs, scaled by 1/sqrt(64)
#pragma unroll
    for (int t = 0; t < 8; t++) {
        int idx = tid + t * 256;       // 0..2047 float4s
        int r  = idx >> 4;             // 0..127
        int c4 = idx & 15;             // 0..15
        float4 v = *(const float4*)(Qg + (size_t)r * D_ + c4 * 4);
        const float sc = 0.125f;
        Qs[(c4 * 4 + 0) * 128 + r] = v.x * sc;
        Qs[(c4 * 4 + 1) * 128 + r] = v.y * sc;
        Qs[(c4 * 4 + 2) * 128 + r] = v.z * sc;
        Qs[(c4 * 4 + 3) * 128 + r] = v.w * sc;
    }

    float o[TM][4];
    float m_i[TM], l_i[TM];
#pragma unroll
    for (int i = 0; i < TM; i++) {
        m_i[i] = -1e30f; l_i[i] = 0.f;
#pragma unroll
        for (int j = 0; j < 4; j++) o[i][j] = 0.f;
    }

    for (int kt = 0; kt < S_ / BKV; kt++) {
        __syncthreads();   // prior iter's Vs/Ps reads done; (kt=0) Qs stores visible

        // Load K tile (transposed) and V tile
#pragma unroll
        for (int t = 0; t < 8; t++) {
            int idx = tid + t * 256;
            int r  = idx >> 4;
            int c4 = idx & 15;
            float4 v = *(const float4*)(Kg + (size_t)(kt * BKV + r) * D_ + c4 * 4);
            Ks[(c4 * 4 + 0) * 128 + r] = v.x;
            Ks[(c4 * 4 + 1) * 128 + r] = v.y;
            Ks[(c4 * 4 + 2) * 128 + r] = v.z;
            Ks[(c4 * 4 + 3) * 128 + r] = v.w;
            float4 w = *(const float4*)(Vg + (size_t)(kt * BKV + r) * D_ + c4 * 4);
            *(float4*)&Vs[r * 64 + c4 * 4] = w;
        }
        __syncthreads();

        // GEMM1: S = (Q/8) K^T  -> acc[8][8]
        float acc[TM][TN];
#pragma unroll
        for (int i = 0; i < TM; i++)
#pragma unroll
            for (int j = 0; j < TN; j++) acc[i][j] = 0.f;

#pragma unroll 4
        for (int kd = 0; kd < DK_; kd++) {
            float ra[8], rb[8];
            *(float4*)&ra[0] = *(const float4*)&Qs[kd * 128 + ty * 8];
            *(float4*)&ra[4] = *(const float4*)&Qs[kd * 128 + ty * 8 + 4];
            *(float4*)&rb[0] = *(const float4*)&Ks[kd * 128 + tx * 8];
            *(float4*)&rb[4] = *(const float4*)&Ks[kd * 128 + tx * 8 + 4];
#pragma unroll
            for (int i = 0; i < 8; i++)
#pragma unroll
                for (int j = 0; j < 8; j++)
                    acc[i][j] = fmaf(ra[i], rb[j], acc[i][j]);
        }

        // Online softmax per row (row owned by 16 threads sharing ty; tx = lane%16)
#pragma unroll
        for (int i = 0; i < TM; i++) {
            float mx = acc[i][0];
#pragma unroll
            for (int j = 1; j < 8; j++) mx = fmaxf(mx, acc[i][j]);
#pragma unroll
            for (int off = 8; off; off >>= 1)
                mx = fmaxf(mx, __shfl_xor_sync(0xffffffffu, mx, off));
            float mnew = fmaxf(m_i[i], mx);
            float corr = __expf(m_i[i] - mnew);
            m_i[i] = mnew;
            float rs = 0.f;
#pragma unroll
            for (int j = 0; j < 8; j++) {
                float p = __expf(acc[i][j] - mnew);
                acc[i][j] = p;
                rs += p;
            }
#pragma unroll
            for (int off = 8; off; off >>= 1)
                rs += __shfl_xor_sync(0xffffffffu, rs, off);
            l_i[i] = l_i[i] * corr + rs;
#pragma unroll
            for (int j = 0; j < 4; j++) o[i][j] *= corr;
            // stage P row-chunk to smem for PV GEMM
            *(float4*)&Ps[(ty * 8 + i) * 128 + tx * 8] =
                make_float4(acc[i][0], acc[i][1], acc[i][2], acc[i][3]);
            *(float4*)&Ps[(ty * 8 + i) * 128 + tx * 8 + 4] =
                make_float4(acc[i][4], acc[i][5], acc[i][6], acc[i][7]);
        }
        __syncthreads();

        // GEMM2: O += P[128,128] * V[128,64]; per-thread cols tx*4..tx*4+3
#pragma unroll 2
        for (int j = 0; j < BKV; j += 4) {
            float4 vv0 = *(const float4*)&Vs[(j + 0) * 64 + tx * 4];
            float4 vv1 = *(const float4*)&Vs[(j + 1) * 64 + tx * 4];
            float4 vv2 = *(const float4*)&Vs[(j + 2) * 64 + tx * 4];
            float4 vv3 = *(const float4*)&Vs[(j + 3) * 64 + tx * 4];
#pragma unroll
            for (int i = 0; i < TM; i++) {
                float4 p4 = *(const float4*)&Ps[(ty * 8 + i) * 128 + j];
                o[i][0] += p4.x * vv0.x + p4.y * vv1.x + p4.z * vv2.x + p4.w * vv3.x;
                o[i][1] += p4.x * vv0.y + p4.y * vv1.y + p4.z * vv2.y + p4.w * vv3.y;
                o[i][2] += p4.x * vv0.z + p4.y * vv1.z + p4.z * vv2.z + p4.w * vv3.z;
                o[i][3] += p4.x * vv0.w + p4.y * vv1.w + p4.z * vv2.w + p4.w * vv3.w;
            }
        }
    }

    // Epilogue: normalize and write heads[b, s, h*64 + vd]
    float* Og = g_heads + ((size_t)b * S_ + qt * BQ) * D_ + h * DK_;
#pragma unroll
    for (int i = 0; i < TM; i++) {
        float inv = 1.f / l_i[i];
        float4 r = make_float4(o[i][0] * inv, o[i][1] * inv, o[i][2] * inv, o[i][3] * inv);
        *(float4*)(Og + (size_t)(ty * 8 + i) * D_ + tx * 4) = r;
    }
}

// ---------------- launch ----------------
extern "C" void kernel_launch(void* const* d_in, const int* in_sizes, int n_in,
                              void* d_out, int out_size) {
    const float* x  = (const float*)d_in[0];
    const float* Wq = (const float*)d_in[1];
    const float* Wk = (const float*)d_in[2];
    const float* Wv = (const float*)d_in[3];
    const float* Wo = (const float*)d_in[4];
    float* out = (float*)d_out;

    void *pWqp, *pWkp, *pWvp, *pQ, *pK, *pV, *pH;
    cudaGetSymbolAddress(&pWqp, g_Wqp);
    cudaGetSymbolAddress(&pWkp, g_Wkp);
    cudaGetSymbolAddress(&pWvp, g_Wvp);
    cudaGetSymbolAddress(&pQ, g_Q);
    cudaGetSymbolAddress(&pK, g_K);
    cudaGetSymbolAddress(&pV, g_V);
    cudaGetSymbolAddress(&pH, g_heads);

    cudaFuncSetAttribute(attention_kernel,
                         cudaFuncAttributeMaxDynamicSharedMemorySize, ATT_SMEM);

    // 1) pack per-head weights into [D, H*64]
    pack_weights<<<(D_ * D_ + 255) / 256, 256>>>(Wq, Wk, Wv);

    // 2) QKV projections: [8192,1024] @ [1024,1024]
    dim3 gproj(D_ / BN, BSZ / BM);   // (8, 64)
    sgemm128<<<gproj, 256>>>(x, (const float*)pWqp, (float*)pQ, BSZ, D_, D_);
    sgemm128<<<gproj, 256>>>(x, (const float*)pWkp, (float*)pK, BSZ, D_, D_);
    sgemm128<<<gproj, 256>>>(x, (const float*)pWvp, (float*)pV, BSZ, D_, D_);

    // 3) flash attention: (q-tiles, heads, batch)
    attention_kernel<<<dim3(S_ / BQ, H_, B_), 256, ATT_SMEM>>>();

    // 4) output projection: heads @ Wo -> out
    sgemm128<<<gproj, 256>>>((const float*)pH, Wo, out, BSZ, D_, D_);
}

// round 3
// speedup vs baseline: 2.7755x; 2.7755x over previous
#include <cuda_runtime.h>
#include <cstdint>
#include <math.h>

// Problem constants
#define B_   4
#define S_   2048
#define D_   1024
#define H_   16
#define DK_  64
#define BSZ  (B_*S_)          // 8192 rows

// ---------------- scratch (no allocations allowed) ----------------
__device__ float g_Wqp[D_*D_];       // [N=H*64, K=D] transposed-packed
__device__ float g_Wkp[D_*D_];
__device__ float g_Wvp[D_*D_];
__device__ float g_Wop[D_*D_];       // Wo^T: [N=D, K=H*64]
__device__ float g_Q[(size_t)BSZ*D_];
__device__ float g_K[(size_t)BSZ*D_];
__device__ float g_V[(size_t)BSZ*D_];
__device__ float g_heads[(size_t)BSZ*D_];

// ================= helpers =================
__device__ __forceinline__ uint32_t smem_u32(const void* p) {
    uint32_t a;
    asm("{ .reg .u64 t; cvta.to.shared.u64 t, %1; cvt.u32.u64 %0, t; }"
        : "=r"(a) : "l"(p));
    return a;
}

__device__ __forceinline__ uint32_t f2tf(float x) {
    uint32_t r;
    asm("cvt.rna.tf32.f32 %0, %1;" : "=r"(r) : "f"(x));
    return r;
}

// m16n8k8 tf32 mma, row.col, fp32 accumulate (sm_80+ baseline ISA)
__device__ __forceinline__ void mma8(float* c, const uint32_t* a,
                                     uint32_t b0, uint32_t b1) {
    asm volatile(
        "mma.sync.aligned.m16n8k8.row.col.f32.tf32.tf32.f32 "
        "{%0,%1,%2,%3},{%4,%5,%6,%7},{%8,%9},{%0,%1,%2,%3};"
        : "+f"(c[0]), "+f"(c[1]), "+f"(c[2]), "+f"(c[3])
        : "r"(a[0]), "r"(a[1]), "r"(a[2]), "r"(a[3]), "r"(b0), "r"(b1));
}

#define CP_ASYNC16(sdst, gsrc) \
    asm volatile("cp.async.cg.shared.global [%0], [%1], 16;" :: "r"(sdst), "l"(gsrc))
#define CP_COMMIT() asm volatile("cp.async.commit_group;" ::: "memory")
#define CP_WAIT1()  asm volatile("cp.async.wait_group 1;" ::: "memory")

// ---------------- weight pack: [H, D, 64] -> [H*64, D] (K-major); Wo -> Wo^T ----------------
__global__ void pack_weights(const float* __restrict__ Wq,
                             const float* __restrict__ Wk,
                             const float* __restrict__ Wv,
                             const float* __restrict__ Wo) {
    int idx = blockIdx.x * blockDim.x + threadIdx.x;
    if (idx >= D_ * D_) return;
    int k = idx & 63;
    int d = (idx >> 6) & (D_ - 1);
    int h = idx >> 16;
    int o = (h * DK_ + k) * D_ + d;
    g_Wqp[o] = Wq[idx];
    g_Wkp[o] = Wk[idx];
    g_Wvp[o] = Wv[idx];
    int r = idx >> 10;
    int c = idx & (D_ - 1);
    g_Wop[c * D_ + r] = Wo[idx];
}

// ================= tf32 mma.sync GEMM =================
// C[M,1024] = A[M,1024] * Bw^T, Bw stored [N=1024, K=1024] row-major (K-major => "col" operand).
// CTA 128x128, BK=32, 8 warps in 4x2 -> warp tile 32x64. Double-buffered cp.async.
#define GBK     32
#define GSTR    36                        // padded k-stride (words): (4*gid+tig)%32 distinct
#define GTILE_W (128 * GSTR)              // words per matrix tile
#define GEMM_SMEM (2 * 2 * GTILE_W * 4)   // 73728 bytes

__global__ __launch_bounds__(256, 2)
void mma_gemm(const float* __restrict__ A, const float* __restrict__ Bw,
              float* __restrict__ C) {
    extern __shared__ float sm[];
    float* AsAll = sm;                      // [2][128*36]
    float* BsAll = sm + 2 * GTILE_W;        // [2][128*36]

    const int tid = threadIdx.x;
    const int lane = tid & 31;
    const int wid = tid >> 5;
    const int gid = lane >> 2;
    const int tig = lane & 3;
    const int wm = wid >> 1;                // 0..3
    const int wn = wid & 1;                 // 0..1
    const int row0 = blockIdx.y * 128;
    const int col0 = blockIdx.x * 128;

    const uint32_t sAs = smem_u32(AsAll);
    const uint32_t sBs = smem_u32(BsAll);

    // stage loader: tile kt (32 k-cols) of A and B into buffer buf
    auto load_stage = [&](int buf, int kt) {
        const float* Ag = A + (size_t)row0 * D_ + kt * GBK;
        const float* Bg = Bw + (size_t)col0 * D_ + kt * GBK;
        uint32_t as = sAs + (uint32_t)buf * GTILE_W * 4;
        uint32_t bs = sBs + (uint32_t)buf * GTILE_W * 4;
#pragma unroll
        for (int it = 0; it < 4; it++) {
            int idx = tid + it * 256;       // 0..1023
            int r  = idx >> 3;              // 0..127
            int c4 = idx & 7;               // 0..7
            uint32_t soff = (uint32_t)(r * GSTR + c4 * 4) * 4;
            CP_ASYNC16(as + soff, Ag + (size_t)r * D_ + c4 * 4);
            CP_ASYNC16(bs + soff, Bg + (size_t)r * D_ + c4 * 4);
        }
    };

    float acc[2][8][4];
#pragma unroll
    for (int mt = 0; mt < 2; mt++)
#pragma unroll
        for (int nt = 0; nt < 8; nt++)
#pragma unroll
            for (int i = 0; i < 4; i++) acc[mt][nt][i] = 0.f;

    load_stage(0, 0);
    CP_COMMIT();

    const int NT = D_ / GBK;                 // 32
    for (int kt = 0; kt < NT; kt++) {
        if (kt + 1 < NT) load_stage((kt + 1) & 1, kt + 1);
        CP_COMMIT();
        CP_WAIT1();
        __syncthreads();

        const float* as = AsAll + (kt & 1) * GTILE_W;
        const float* bs = BsAll + (kt & 1) * GTILE_W;
#pragma unroll
        for (int ks = 0; ks < 4; ks++) {
            const int k0 = ks * 8;
            uint32_t afr[2][4];
#pragma unroll
            for (int mt = 0; mt < 2; mt++) {
                int mr = wm * 32 + mt * 16 + gid;
                afr[mt][0] = f2tf(as[(mr)     * GSTR + k0 + tig]);
                afr[mt][1] = f2tf(as[(mr + 8) * GSTR + k0 + tig]);
                afr[mt][2] = f2tf(as[(mr)     * GSTR + k0 + tig + 4]);
                afr[mt][3] = f2tf(as[(mr + 8) * GSTR + k0 + tig + 4]);
            }
#pragma unroll
            for (int nt = 0; nt < 8; nt++) {
                int nr = wn * 64 + nt * 8 + gid;
                uint32_t b0 = f2tf(bs[nr * GSTR + k0 + tig]);
                uint32_t b1 = f2tf(bs[nr * GSTR + k0 + tig + 4]);
                mma8(acc[0][nt], afr[0], b0, b1);
                mma8(acc[1][nt], afr[1], b0, b1);
            }
        }
        __syncthreads();
    }

    // epilogue: float2 stores (rows: gid, gid+8; cols: 8nt + 2tig)
#pragma unroll
    for (int mt = 0; mt < 2; mt++) {
        int mr = row0 + wm * 32 + mt * 16 + gid;
#pragma unroll
        for (int nt = 0; nt < 8; nt++) {
            int cc = col0 + wn * 64 + nt * 8 + 2 * tig;
            *(float2*)(C + (size_t)mr * D_ + cc) =
                make_float2(acc[mt][nt][0], acc[mt][nt][1]);
            *(float2*)(C + (size_t)(mr + 8) * D_ + cc) =
                make_float2(acc[mt][nt][2], acc[mt][nt][3]);
        }
    }
}

// ================= flash attention with tf32 mma.sync =================
// CTA = (qtile 128, head, batch), 256 threads / 8 warps.
// Warp w owns query rows 16w..16w+15 for BOTH GEMMs -> softmax never crosses warps.
// Smem (tf32-converted uint32 payloads stored as float):
//   Qs [128][68]   (q rows, k=64 padded to 68)
//   Ks [128][68]   (key rows, natural K-major; B operand of QK^T)
//   Vs [64][132]   (V transposed: [v][s])
//   Ps [128][132]  (P tile, A operand of PV)
#define QS_STR 68
#define VS_STR 132
#define ATT_W  (128*QS_STR + 128*QS_STR + 64*VS_STR + 128*VS_STR)
#define ATT_SMEM (ATT_W * 4)     // 171008 bytes

__global__ __launch_bounds__(256, 1)
void attention_mma() {
    extern __shared__ float sm[];
    float* Qs = sm;                        // [128][68]
    float* Ks = Qs + 128 * QS_STR;         // [128][68]
    float* Vs = Ks + 128 * QS_STR;         // [64][132]
    float* Ps = Vs + 64 * VS_STR;          // [128][132]

    const int tid = threadIdx.x;
    const int lane = tid & 31;
    const int wid = tid >> 5;
    const int gid = lane >> 2;
    const int tig = lane & 3;
    const int qt = blockIdx.x;
    const int h  = blockIdx.y;
    const int b  = blockIdx.z;

    const float* Qg = g_Q + ((size_t)b * S_ + qt * 128) * D_ + h * DK_;
    const float* Kg = g_K + ((size_t)b * S_) * D_ + h * DK_;
    const float* Vg = g_V + ((size_t)b * S_) * D_ + h * DK_;

    // load Q tile (scaled, tf32)
#pragma unroll
    for (int it = 0; it < 8; it++) {
        int idx = tid + it * 256;   // 0..2047
        int r  = idx >> 4;          // 0..127
        int c4 = idx & 15;          // 0..15
        float4 v = *(const float4*)(Qg + (size_t)r * D_ + c4 * 4);
        uint32_t* q = (uint32_t*)&Qs[r * QS_STR + c4 * 4];
        q[0] = f2tf(v.x * 0.125f);
        q[1] = f2tf(v.y * 0.125f);
        q[2] = f2tf(v.z * 0.125f);
        q[3] = f2tf(v.w * 0.125f);
    }

    float O[8][4];
#pragma unroll
    for (int nt = 0; nt < 8; nt++)
#pragma unroll
        for (int i = 0; i < 4; i++) O[nt][i] = 0.f;
    float m0 = -1e30f, m1 = -1e30f, l0 = 0.f, l1 = 0.f;

    for (int kt = 0; kt < S_ / 128; kt++) {
        __syncthreads();   // prior iter's Ks/Vs reads complete (and Qs ready at kt=0)

        // load K tile (natural layout) and V tile (transposed)
#pragma unroll
        for (int it = 0; it < 8; it++) {
            int idx = tid + it * 256;
            int r  = idx >> 4;
            int c4 = idx & 15;
            float4 v = *(const float4*)(Kg + (size_t)(kt * 128 + r) * D_ + c4 * 4);
            uint32_t* kk = (uint32_t*)&Ks[r * QS_STR + c4 * 4];
            kk[0] = f2tf(v.x); kk[1] = f2tf(v.y); kk[2] = f2tf(v.z); kk[3] = f2tf(v.w);
            float4 w = *(const float4*)(Vg + (size_t)(kt * 128 + r) * D_ + c4 * 4);
            ((uint32_t*)Vs)[(c4 * 4 + 0) * VS_STR + r] = f2tf(w.x);
            ((uint32_t*)Vs)[(c4 * 4 + 1) * VS_STR + r] = f2tf(w.y);
            ((uint32_t*)Vs)[(c4 * 4 + 2) * VS_STR + r] = f2tf(w.z);
            ((uint32_t*)Vs)[(c4 * 4 + 3) * VS_STR + r] = f2tf(w.w);
        }
        __syncthreads();

        // GEMM1: S[16][128] per warp = Q rows x K^T
        float S[16][4];
#pragma unroll
        for (int nt = 0; nt < 16; nt++)
#pragma unroll
            for (int i = 0; i < 4; i++) S[nt][i] = 0.f;

        const uint32_t* Qu = (const uint32_t*)Qs;
        const uint32_t* Ku = (const uint32_t*)Ks;
#pragma unroll
        for (int ks = 0; ks < 8; ks++) {
            const int k0 = ks * 8;
            int mr = wid * 16 + gid;
            uint32_t a[4];
            a[0] = Qu[(mr)     * QS_STR + k0 + tig];
            a[1] = Qu[(mr + 8) * QS_STR + k0 + tig];
            a[2] = Qu[(mr)     * QS_STR + k0 + tig + 4];
            a[3] = Qu[(mr + 8) * QS_STR + k0 + tig + 4];
#pragma unroll
            for (int nt = 0; nt < 16; nt++) {
                int nr = nt * 8 + gid;
                uint32_t b0 = Ku[nr * QS_STR + k0 + tig];
                uint32_t b1 = Ku[nr * QS_STR + k0 + tig + 4];
                mma8(S[nt], a, b0, b1);
            }
        }

        // online softmax: thread owns rows r0=16w+gid (c0,c1) and r1=r0+8 (c2,c3)
        float mx0 = -1e30f, mx1 = -1e30f;
#pragma unroll
        for (int nt = 0; nt < 16; nt++) {
            mx0 = fmaxf(mx0, fmaxf(S[nt][0], S[nt][1]));
            mx1 = fmaxf(mx1, fmaxf(S[nt][2], S[nt][3]));
        }
#pragma unroll
        for (int off = 1; off <= 2; off <<= 1) {
            mx0 = fmaxf(mx0, __shfl_xor_sync(0xffffffffu, mx0, off));
            mx1 = fmaxf(mx1, __shfl_xor_sync(0xffffffffu, mx1, off));
        }
        float mn0 = fmaxf(m0, mx0), mn1 = fmaxf(m1, mx1);
        float cr0 = __expf(m0 - mn0), cr1 = __expf(m1 - mn1);
        m0 = mn0; m1 = mn1;

        float s0 = 0.f, s1 = 0.f;
        uint32_t* Pu = (uint32_t*)Ps;
        int r0 = wid * 16 + gid;
#pragma unroll
        for (int nt = 0; nt < 16; nt++) {
            float p0 = __expf(S[nt][0] - mn0);
            float p1 = __expf(S[nt][1] - mn0);
            float p2 = __expf(S[nt][2] - mn1);
            float p3 = __expf(S[nt][3] - mn1);
            s0 += p0 + p1;
            s1 += p2 + p3;
            int cc = nt * 8 + 2 * tig;
            *(uint2*)&Pu[(r0)     * VS_STR + cc] = make_uint2(f2tf(p0), f2tf(p1));
            *(uint2*)&Pu[(r0 + 8) * VS_STR + cc] = make_uint2(f2tf(p2), f2tf(p3));
        }
#pragma unroll
        for (int off = 1; off <= 2; off <<= 1) {
            s0 += __shfl_xor_sync(0xffffffffu, s0, off);
            s1 += __shfl_xor_sync(0xffffffffu, s1, off);
        }
        l0 = l0 * cr0 + s0;
        l1 = l1 * cr1 + s1;
#pragma unroll
        for (int nt = 0; nt < 8; nt++) {
            O[nt][0] *= cr0; O[nt][1] *= cr0;
            O[nt][2] *= cr1; O[nt][3] *= cr1;
        }
        __syncwarp();   // warp reads only its own Ps rows

        // GEMM2: O[16][64] per warp += P[16][128] x V[128][64]
        const uint32_t* Vu = (const uint32_t*)Vs;
#pragma unroll
        for (int ks = 0; ks < 16; ks++) {
            const int k0 = ks * 8;
            uint32_t a[4];
            a[0] = Pu[(r0)     * VS_STR + k0 + tig];
            a[1] = Pu[(r0 + 8) * VS_STR + k0 + tig];
            a[2] = Pu[(r0)     * VS_STR + k0 + tig + 4];
            a[3] = Pu[(r0 + 8) * VS_STR + k0 + tig + 4];
#pragma unroll
            for (int nt = 0; nt < 8; nt++) {
                int nr = nt * 8 + gid;
                uint32_t b0 = Vu[nr * VS_STR + k0 + tig];
                uint32_t b1 = Vu[nr * VS_STR + k0 + tig + 4];
                mma8(O[nt], a, b0, b1);
            }
        }
    }

    // epilogue
    float inv0 = 1.f / l0, inv1 = 1.f / l1;
    float* Og = g_heads + ((size_t)b * S_ + qt * 128) * D_ + h * DK_;
    int r0 = wid * 16 + gid;
#pragma unroll
    for (int nt = 0; nt < 8; nt++) {
        int cc = nt * 8 + 2 * tig;
        *(float2*)(Og + (size_t)r0 * D_ + cc) =
            make_float2(O[nt][0] * inv0, O[nt][1] * inv0);
        *(float2*)(Og + (size_t)(r0 + 8) * D_ + cc) =
            make_float2(O[nt][2] * inv1, O[nt][3] * inv1);
    }
}

// ---------------- launch ----------------
extern "C" void kernel_launch(void* const* d_in, const int* in_sizes, int n_in,
                              void* d_out, int out_size) {
    const float* x  = (const float*)d_in[0];
    const float* Wq = (const float*)d_in[1];
    const float* Wk = (const float*)d_in[2];
    const float* Wv = (const float*)d_in[3];
    const float* Wo = (const float*)d_in[4];
    float* out = (float*)d_out;

    void *pWqp, *pWkp, *pWvp, *pWop, *pQ, *pK, *pV, *pH;
    cudaGetSymbolAddress(&pWqp, g_Wqp);
    cudaGetSymbolAddress(&pWkp, g_Wkp);
    cudaGetSymbolAddress(&pWvp, g_Wvp);
    cudaGetSymbolAddress(&pWop, g_Wop);
    cudaGetSymbolAddress(&pQ, g_Q);
    cudaGetSymbolAddress(&pK, g_K);
    cudaGetSymbolAddress(&pV, g_V);
    cudaGetSymbolAddress(&pH, g_heads);

    cudaFuncSetAttribute(mma_gemm,
                         cudaFuncAttributeMaxDynamicSharedMemorySize, GEMM_SMEM);
    cudaFuncSetAttribute(attention_mma,
                         cudaFuncAttributeMaxDynamicSharedMemorySize, ATT_SMEM);

    pack_weights<<<(D_ * D_ + 255) / 256, 256>>>(Wq, Wk, Wv, Wo);

    dim3 gproj(D_ / 128, BSZ / 128);   // (8, 64)
    mma_gemm<<<gproj, 256, GEMM_SMEM>>>(x, (const float*)pWqp, (float*)pQ);
    mma_gemm<<<gproj, 256, GEMM_SMEM>>>(x, (const float*)pWkp, (float*)pK);
    mma_gemm<<<gproj, 256, GEMM_SMEM>>>(x, (const float*)pWvp, (float*)pV);

    attention_mma<<<dim3(S_ / 128, H_, B_), 256, ATT_SMEM>>>();

    mma_gemm<<<gproj, 256, GEMM_SMEM>>>((const float*)pH, (const float*)pWop, out);
}